// round 5
// baseline (speedup 1.0000x reference)
#include <cuda_runtime.h>
#include <math.h>
#include <stdint.h>

#define BB 16
#define TT 28
#define NN 2048
#define HH 32
#define LL 8

// -------- scratch (device globals) --------
// g_Q: natural [b][n][h], tf32-rounded, pre-scaled by (1-geo)/sqrt(H)*log2e
// g_K: [b][n][pi(h)]  pi(h) = (h%4)*8 + h/4      (K fragment vectorization)
// g_V: [b][permrow(n)][sigma(h)]  sigma(h) = (h%8)*4 + h/8, rows permuted within 8-groups
__device__ float g_Q[BB*NN*HH];
__device__ float g_K[BB*NN*HH];
__device__ float g_V[BB*NN*HH];
__device__ float g_ds[BB*NN];

__device__ __forceinline__ float tf32r(float f){
    uint32_t u; asm("cvt.rna.tf32.f32 %0,%1;" : "=r"(u) : "f"(f));
    return __uint_as_float(u);
}
__device__ __forceinline__ float ex2(float x){
    float y; asm("ex2.approx.f32 %0,%1;" : "=f"(y) : "f"(x)); return y;
}
__device__ __forceinline__ void mma_tf32(float d[4], const uint32_t a[4], uint32_t b0, uint32_t b1){
    asm("mma.sync.aligned.m16n8k8.row.col.f32.tf32.tf32.f32 "
        "{%0,%1,%2,%3},{%4,%5,%6,%7},{%8,%9},{%0,%1,%2,%3};"
        : "+f"(d[0]),"+f"(d[1]),"+f"(d[2]),"+f"(d[3])
        : "r"(a[0]),"r"(a[1]),"r"(a[2]),"r"(a[3]),"r"(b0),"r"(b1));
}
__device__ __forceinline__ void cpa16(uint32_t s, const float* g){
    asm volatile("cp.async.cg.shared.global [%0],[%1],16;" :: "r"(s), "l"(g));
}

// =====================================================================
// Kernel 1: delayed signal
// =====================================================================
__global__ void ds_kernel(const float* __restrict__ x, const float* __restrict__ logits)
{
    int b = blockIdx.y;
    int n = blockIdx.x * 256 + threadIdx.x;
    float lw[LL];
    float m = -1e30f;
#pragma unroll
    for (int t = 0; t < LL; t++) { lw[t] = logits[t]; m = fmaxf(m, lw[t]); }
    float s = 0.f, e[LL];
#pragma unroll
    for (int t = 0; t < LL; t++) { e[t] = expf(lw[t] - m); s += e[t]; }
    float inv = 1.f / s;
    float acc = 0.f;
#pragma unroll
    for (int tau = 0; tau < LL; tau++)
        acc += e[tau] * inv * x[((size_t)b * TT + (TT - 1 - tau)) * NN + n];
    g_ds[b * NN + n] = acc;
}

// =====================================================================
// Kernel 2: QKV projections; K/V written in mma-fragment-friendly layouts.
// =====================================================================
__global__ void qkv_kernel(const float* __restrict__ features,
                           const float* __restrict__ Wq, const float* __restrict__ bq,
                           const float* __restrict__ Wk, const float* __restrict__ bk,
                           const float* __restrict__ Wv, const float* __restrict__ bv,
                           const float* __restrict__ gw)
{
    __shared__ float Ws[3][1024];
    __shared__ float bs[3][32];
    __shared__ float stg[256 * 33];

    int b = blockIdx.y;
    int n0 = blockIdx.x * 256;
    int tid = threadIdx.x;

    for (int i = tid; i < 1024; i += 256) {
        Ws[0][i] = Wq[i]; Ws[1][i] = Wk[i]; Ws[2][i] = Wv[i];
    }
    if (tid < 32) { bs[0][tid] = bq[tid]; bs[1][tid] = bk[tid]; bs[2][tid] = bv[tid]; }
    __syncthreads();

    float geo = 1.f / (1.f + expf(-gw[0]));
    float csq = (1.f - geo) * 0.17677669529663687f * 1.4426950408889634f;

    int n = n0 + tid;
    float4 rf[8];
    const float* fp = features + ((size_t)b * NN + n) * HH;
#pragma unroll
    for (int i = 0; i < 8; i++) rf[i] = *(const float4*)(fp + i * 4);

    float* outp[3] = { g_Q, g_K, g_V };
    for (int pass = 0; pass < 3; pass++) {
#pragma unroll 4
        for (int j = 0; j < 32; j++) {
            float a = bs[pass][j];
#pragma unroll
            for (int i = 0; i < 8; i++) {
                float4 w4 = *(float4*)&Ws[pass][j * 32 + i * 4];
                a += rf[i].x * w4.x + rf[i].y * w4.y + rf[i].z * w4.z + rf[i].w * w4.w;
            }
            if (pass == 0) a *= csq;
            int col = (pass == 0) ? j
                    : (pass == 1) ? ((j & 3) * 8 + (j >> 2))
                                  : ((j & 7) * 4 + (j >> 3));
            stg[tid * 33 + col] = tf32r(a);
        }
        __syncthreads();
        float* op = outp[pass];
        for (int ch = 0; ch < 32; ch++) {
            int idx = ch * 256 + tid;
            int r = idx >> 5, h = idx & 31;
            int rr = r;
            if (pass == 2) {
                int w = r & 7;
                rr = (r & ~7) | ((w & 1) ? (w >> 1) + 4 : (w >> 1));
            }
            op[((size_t)b * NN + n0 + rr) * HH + h] = stg[r * 33 + h];
        }
        __syncthreads();
    }
}

// =====================================================================
// Kernel 3: tf32 mma flash attention, cp.async double-buffered 128-key tiles.
// =====================================================================
#define OFF_Q   0           // [128][36]
#define OFF_K0  4608        // [128][36]
#define OFF_K1  9216
#define OFF_V0  13824       // [128][40]
#define OFF_V1  18944
#define OFF_DS  24064       // [2048]
#define OFF_LS  26112       // [2][128]
#define OFF_PR  26368       // [2][128]
#define SMF     26624
#define SMEM_BYTES (SMF * 4)
// epilogue aliases (mainloop smem dead)
#define OFF_PART 0          // [128][34]
#define OFF_CS   4608       // [128][33]
#define OFF_WOS  9216       // [32][33]
#define OFF_BOS  10272
#define OFF_GMS  10304
#define OFF_BTS  10336

__global__ void __launch_bounds__(256, 2) attn_kernel(
    const float* __restrict__ adj, const float* __restrict__ features,
    const float* __restrict__ gw,  const float* __restrict__ Wo,
    const float* __restrict__ bo,  const float* __restrict__ gamma,
    const float* __restrict__ beta, float* __restrict__ out)
{
    extern __shared__ float sm[];
    uint32_t* smu = (uint32_t*)sm;
    uint32_t smb = (uint32_t)__cvta_generic_to_shared(sm);

    const int b    = blockIdx.y;
    const int n0   = blockIdx.x * 128;
    const int tid  = threadIdx.x;
    const int warp = tid >> 5, lane = tid & 31;
    const int wr   = warp >> 1, wc = warp & 1;
    const int g    = lane >> 2, q = lane & 3;
    const int rowbase = wr * 32;

    const float LOG2E = 1.4426950408889634f;
    float geo = 1.f / (1.f + expf(-gw[0]));
    float cg  = geo * 5.f * LOG2E;

    const float* gK = &g_K[(size_t)b * NN * HH];
    const float* gV = &g_V[(size_t)b * NN * HH];

    // ---- preload tile 0 via cp.async ----
    {
        const float* k0 = gK;   // rows 0..127
        const float* v0 = gV;
#pragma unroll
        for (int j = 0; j < 4; j++) {
            int c = j * 256 + tid;
            int row = c >> 3, col = (c & 7) * 4;
            cpa16(smb + (OFF_K0 + row * 36 + col) * 4, k0 + c * 4);
            cpa16(smb + (OFF_V0 + row * 40 + col) * 4, v0 + c * 4);
        }
        asm volatile("cp.async.commit_group;");
    }

    // ---- Q tile + full ds row into smem ----
    for (int i = tid; i < 1024; i += 256) {
        int r = i >> 3, h4 = (i & 7) * 4;
        *(float4*)&sm[OFF_Q + r * 36 + h4] =
            *(const float4*)&g_Q[((size_t)b * NN + n0 + r) * HH + h4];
    }
    for (int i = tid; i < 512; i += 256)
        *(float4*)&sm[OFF_DS + i * 4] = *(const float4*)&g_ds[(size_t)b * NN + i * 4];
    __syncthreads();

    // ---- Q fragments (register-resident) ----
    uint32_t qa[2][4][4];
#pragma unroll
    for (int mi = 0; mi < 2; mi++)
#pragma unroll
        for (int kk = 0; kk < 4; kk++) {
            int r = rowbase + mi * 16 + g;
            qa[mi][kk][0] = smu[OFF_Q + r       * 36 + kk * 8 + q];
            qa[mi][kk][1] = smu[OFF_Q + (r + 8) * 36 + kk * 8 + q];
            qa[mi][kk][2] = smu[OFF_Q + r       * 36 + kk * 8 + q + 4];
            qa[mi][kk][3] = smu[OFF_Q + (r + 8) * 36 + kk * 8 + q + 4];
        }

    float av[2][4][4];
#pragma unroll
    for (int mi = 0; mi < 2; mi++)
#pragma unroll
        for (int ht = 0; ht < 4; ht++)
#pragma unroll
            for (int e = 0; e < 4; e++) av[mi][ht][e] = 0.f;
    float lr[2][2] = {{0.f,0.f},{0.f,0.f}}, prr[2][2] = {{0.f,0.f},{0.f,0.f}};

    for (int it = 0; it < NN / 128; it++) {
        const int kb = (it & 1) ? OFF_K1 : OFF_K0;
        const int vb = (it & 1) ? OFF_V1 : OFF_V0;
        if (it + 1 < NN / 128) {
            const int kn = (it & 1) ? OFF_K0 : OFF_K1;
            const int vn = (it & 1) ? OFF_V0 : OFF_V1;
            const float* kp = gK + (size_t)(it + 1) * 128 * HH;
            const float* vp = gV + (size_t)(it + 1) * 128 * HH;
#pragma unroll
            for (int j = 0; j < 4; j++) {
                int c = j * 256 + tid;
                int row = c >> 3, col = (c & 7) * 4;
                cpa16(smb + (kn + row * 36 + col) * 4, kp + c * 4);
                cpa16(smb + (vn + row * 40 + col) * 4, vp + c * 4);
            }
            asm volatile("cp.async.commit_group;");
            asm volatile("cp.async.wait_group 1;");
        } else {
            asm volatile("cp.async.wait_group 0;");
        }
        __syncthreads();

#pragma unroll
        for (int s = 0; s < 2; s++) {
            const int m0 = it * 128 + s * 64;
            // adj -> S accumulator init (log2 domain)
            float sd[2][4][4];
#pragma unroll
            for (int mi = 0; mi < 2; mi++)
#pragma unroll
                for (int nt = 0; nt < 4; nt++) {
                    size_t r0 = (size_t)(n0 + rowbase + mi * 16 + g) * NN + m0 + wc * 32 + nt * 8 + 2 * q;
                    float2 a0 = *(const float2*)&adj[r0];
                    float2 a1 = *(const float2*)&adj[r0 + 8 * NN];
                    sd[mi][nt][0] = cg * a0.x; sd[mi][nt][1] = cg * a0.y;
                    sd[mi][nt][2] = cg * a1.x; sd[mi][nt][3] = cg * a1.y;
                }

            // ---- S = Q K^T (+adj in C) ----
#pragma unroll
            for (int nt = 0; nt < 4; nt++) {
                int kr = s * 64 + wc * 32 + nt * 8 + g;
                float4 ka = *(float4*)&sm[kb + kr * 36 + q * 8];
                float4 kx = *(float4*)&sm[kb + kr * 36 + q * 8 + 4];
                uint32_t b00 = __float_as_uint(ka.x), b01 = __float_as_uint(ka.y);
                uint32_t b10 = __float_as_uint(ka.z), b11 = __float_as_uint(ka.w);
                uint32_t b20 = __float_as_uint(kx.x), b21 = __float_as_uint(kx.y);
                uint32_t b30 = __float_as_uint(kx.z), b31 = __float_as_uint(kx.w);
                mma_tf32(sd[0][nt], qa[0][0], b00, b01);
                mma_tf32(sd[1][nt], qa[1][0], b00, b01);
                mma_tf32(sd[0][nt], qa[0][1], b10, b11);
                mma_tf32(sd[1][nt], qa[1][1], b10, b11);
                mma_tf32(sd[0][nt], qa[0][2], b20, b21);
                mma_tf32(sd[1][nt], qa[1][2], b20, b21);
                mma_tf32(sd[0][nt], qa[0][3], b30, b31);
                mma_tf32(sd[1][nt], qa[1][3], b30, b31);
            }

            // ---- p = exp2(s); accumulate l, pr ----
#pragma unroll
            for (int nt = 0; nt < 4; nt++) {
                float2 dsp = *(const float2*)&sm[OFF_DS + m0 + wc * 32 + nt * 8 + 2 * q];
#pragma unroll
                for (int mi = 0; mi < 2; mi++) {
                    float p0 = ex2(sd[mi][nt][0]);
                    float p1 = ex2(sd[mi][nt][1]);
                    float p2 = ex2(sd[mi][nt][2]);
                    float p3 = ex2(sd[mi][nt][3]);
                    sd[mi][nt][0] = p0; sd[mi][nt][1] = p1;
                    sd[mi][nt][2] = p2; sd[mi][nt][3] = p3;
                    lr[mi][0] += p0 + p1;
                    lr[mi][1] += p2 + p3;
                    prr[mi][0] += p0 * dsp.x + p1 * dsp.y;
                    prr[mi][1] += p2 * dsp.x + p3 * dsp.y;
                }
            }

            // ---- attended += P V ----
#pragma unroll
            for (int nt = 0; nt < 4; nt++) {
                uint32_t pa0[4] = { __float_as_uint(sd[0][nt][0]), __float_as_uint(sd[0][nt][2]),
                                    __float_as_uint(sd[0][nt][1]), __float_as_uint(sd[0][nt][3]) };
                uint32_t pa1[4] = { __float_as_uint(sd[1][nt][0]), __float_as_uint(sd[1][nt][2]),
                                    __float_as_uint(sd[1][nt][1]), __float_as_uint(sd[1][nt][3]) };
                int vr = s * 64 + wc * 32 + nt * 8 + q;
                float4 va = *(float4*)&sm[vb + vr * 40 + g * 4];
                float4 vx = *(float4*)&sm[vb + (vr + 4) * 40 + g * 4];
                uint32_t v00 = __float_as_uint(va.x), v10 = __float_as_uint(va.y);
                uint32_t v20 = __float_as_uint(va.z), v30 = __float_as_uint(va.w);
                uint32_t v01 = __float_as_uint(vx.x), v11 = __float_as_uint(vx.y);
                uint32_t v21 = __float_as_uint(vx.z), v31 = __float_as_uint(vx.w);
                mma_tf32(av[0][0], pa0, v00, v01);
                mma_tf32(av[1][0], pa1, v00, v01);
                mma_tf32(av[0][1], pa0, v10, v11);
                mma_tf32(av[1][1], pa1, v10, v11);
                mma_tf32(av[0][2], pa0, v20, v21);
                mma_tf32(av[1][2], pa1, v20, v21);
                mma_tf32(av[0][3], pa0, v30, v31);
                mma_tf32(av[1][3], pa1, v30, v31);
            }
        }
        __syncthreads();   // all warps done with this buffer before it is refilled
    }

    // ---- epilogue ----
#pragma unroll
    for (int mi = 0; mi < 2; mi++)
#pragma unroll
        for (int j = 0; j < 2; j++) {
            float v = lr[mi][j];
            v += __shfl_xor_sync(0xffffffffu, v, 1);
            v += __shfl_xor_sync(0xffffffffu, v, 2);
            lr[mi][j] = v;
            float w = prr[mi][j];
            w += __shfl_xor_sync(0xffffffffu, w, 1);
            w += __shfl_xor_sync(0xffffffffu, w, 2);
            prr[mi][j] = w;
        }

    if (q == 0) {
#pragma unroll
        for (int mi = 0; mi < 2; mi++) {
            int r = rowbase + mi * 16 + g;
            sm[OFF_LS + wc * 128 + r]     = lr[mi][0];
            sm[OFF_LS + wc * 128 + r + 8] = lr[mi][1];
            sm[OFF_PR + wc * 128 + r]     = prr[mi][0];
            sm[OFF_PR + wc * 128 + r + 8] = prr[mi][1];
        }
    }
    if (wc == 0) {
#pragma unroll
        for (int mi = 0; mi < 2; mi++) {
            int r = rowbase + mi * 16 + g;
#pragma unroll
            for (int ht = 0; ht < 4; ht++) {
                *(float2*)&sm[OFF_PART + r * 34 + ht * 8 + 2 * q] =
                    make_float2(av[mi][ht][0], av[mi][ht][1]);
                *(float2*)&sm[OFF_PART + (r + 8) * 34 + ht * 8 + 2 * q] =
                    make_float2(av[mi][ht][2], av[mi][ht][3]);
            }
        }
    }
    for (int i = tid; i < 1024; i += 256)
        sm[OFF_WOS + (i >> 5) * 33 + (i & 31)] = Wo[i];
    if (tid < 32) {
        sm[OFF_BOS + tid] = bo[tid];
        sm[OFF_GMS + tid] = gamma[tid];
        sm[OFF_BTS + tid] = beta[tid];
    }
    __syncthreads();
    if (wc == 1) {
#pragma unroll
        for (int mi = 0; mi < 2; mi++) {
            int r = rowbase + mi * 16 + g;
#pragma unroll
            for (int ht = 0; ht < 4; ht++) {
                float* p0 = &sm[OFF_PART + r * 34 + ht * 8 + 2 * q];
                p0[0] += av[mi][ht][0]; p0[1] += av[mi][ht][1];
                float* p1 = &sm[OFF_PART + (r + 8) * 34 + ht * 8 + 2 * q];
                p1[0] += av[mi][ht][2]; p1[1] += av[mi][ht][3];
            }
        }
    }
    __syncthreads();

    // combined = features + attended/l + 0.1*pr/l
    {
        int r = tid >> 1, h0 = (tid & 1) * 16;
        float l    = sm[OFF_LS + r] + sm[OFF_LS + 128 + r];
        float invl = 1.f / l;
        float pv   = (sm[OFF_PR + r] + sm[OFF_PR + 128 + r]) * invl * 0.1f;
        const float* fp = &features[((size_t)b * NN + n0 + r) * HH + h0];
#pragma unroll
        for (int h4 = 0; h4 < 16; h4 += 4) {
            float4 f4 = *(const float4*)(fp + h4);
            float fe[4] = { f4.x, f4.y, f4.z, f4.w };
#pragma unroll
            for (int e = 0; e < 4; e++) {
                int h = h0 + h4 + e;
                sm[OFF_CS + r * 33 + h] = fe[e] + sm[OFF_PART + r * 34 + h] * invl + pv;
            }
        }
    }
    __syncthreads();

    // out-proj + LayerNorm (one row per thread)
    if (tid < 128) {
        float cr[32], ho[32];
#pragma unroll
        for (int h = 0; h < 32; h++) cr[h] = sm[OFF_CS + tid * 33 + h];
        float mu = 0.f;
#pragma unroll
        for (int j = 0; j < 32; j++) {
            float a = sm[OFF_BOS + j];
#pragma unroll
            for (int h = 0; h < 32; h++) a += cr[h] * sm[OFF_WOS + j * 33 + h];
            ho[j] = a; mu += a;
        }
        mu *= 0.03125f;
        float var = 0.f;
#pragma unroll
        for (int j = 0; j < 32; j++) { float d = ho[j] - mu; var += d * d; }
        var *= 0.03125f;
        float rs = rsqrtf(var + 1e-5f);
        float* op = out + ((size_t)b * NN + n0 + tid) * HH;
#pragma unroll
        for (int j4 = 0; j4 < 32; j4 += 4) {
            float4 o4;
            o4.x = (ho[j4 + 0] - mu) * rs * sm[OFF_GMS + j4 + 0] + sm[OFF_BTS + j4 + 0];
            o4.y = (ho[j4 + 1] - mu) * rs * sm[OFF_GMS + j4 + 1] + sm[OFF_BTS + j4 + 1];
            o4.z = (ho[j4 + 2] - mu) * rs * sm[OFF_GMS + j4 + 2] + sm[OFF_BTS + j4 + 2];
            o4.w = (ho[j4 + 3] - mu) * rs * sm[OFF_GMS + j4 + 3] + sm[OFF_BTS + j4 + 3];
            *(float4*)(op + j4) = o4;
        }
    }
}

// =====================================================================
extern "C" void kernel_launch(void* const* d_in, const int* in_sizes, int n_in,
                              void* d_out, int out_size)
{
    const float* x        = (const float*)d_in[0];
    const float* features = (const float*)d_in[1];
    const float* dlog     = (const float*)d_in[2];
    const float* Wq       = (const float*)d_in[3];
    const float* bq       = (const float*)d_in[4];
    const float* Wk       = (const float*)d_in[5];
    const float* bk       = (const float*)d_in[6];
    const float* Wv       = (const float*)d_in[7];
    const float* bv       = (const float*)d_in[8];
    const float* adj      = (const float*)d_in[9];
    const float* gw       = (const float*)d_in[10];
    const float* Wo       = (const float*)d_in[11];
    const float* bo       = (const float*)d_in[12];
    const float* gamma    = (const float*)d_in[13];
    const float* beta     = (const float*)d_in[14];
    float* out = (float*)d_out;

    cudaFuncSetAttribute(attn_kernel, cudaFuncAttributeMaxDynamicSharedMemorySize, SMEM_BYTES);

    ds_kernel<<<dim3(NN / 256, BB), 256>>>(x, dlog);
    qkv_kernel<<<dim3(NN / 256, BB), 256>>>(features, Wq, bq, Wk, bk, Wv, bv, gw);
    attn_kernel<<<dim3(NN / 128, BB), 256, SMEM_BYTES>>>(adj, features, gw, Wo, bo, gamma, beta, out);
}